// round 4
// baseline (speedup 1.0000x reference)
#include <cuda_runtime.h>

#define NTOK 4096

// scratch: qkv = [b][192][4096] (q:0-63, k:64-127, v:128-191)
__device__ float g_qkv[4][192][NTOK];
__device__ float g_att[4][64][NTOK];
__device__ float g_part[2][4][64][NTOK];   // split-KV unnormalized O
__device__ float g_ml[2][4][2][NTOK];      // [h][b][{m,l}][n]

// ---- tf32 helpers ----
__device__ __forceinline__ unsigned cvt_tf32u(float x){
  unsigned u; asm("cvt.rna.tf32.f32 %0, %1;" : "=r"(u) : "f"(x)); return u;
}
__device__ __forceinline__ float cvt_tf32f(float x){
  return __uint_as_float(cvt_tf32u(x));
}
__device__ __forceinline__ void split_tf32(float x, unsigned &hi, unsigned &lo){
  hi = cvt_tf32u(x);
  lo = cvt_tf32u(x - __uint_as_float(hi));
}
__device__ __forceinline__ void mma_tf32(float d[4],
    unsigned a0, unsigned a1, unsigned a2, unsigned a3,
    unsigned b0, unsigned b1){
  asm("mma.sync.aligned.m16n8k8.row.col.f32.tf32.tf32.f32 "
      "{%0,%1,%2,%3}, {%4,%5,%6,%7}, {%8,%9}, {%0,%1,%2,%3};"
      : "+f"(d[0]), "+f"(d[1]), "+f"(d[2]), "+f"(d[3])
      : "r"(a0), "r"(a1), "r"(a2), "r"(a3), "r"(b0), "r"(b1));
}

// ---------------------------------------------------------------------------
// Projection GEMM, tf32 mma with hi/lo compensation (fp32-accurate).
// out[b][o][n] = bias[o] + sum_k W[o][k] * X[b][k][n]
// grid (N/64, M/64, B), 256 threads (8 warps, 4x2: wm rows, wn cols).
// ---------------------------------------------------------------------------
#define WS_STR 68
#define XS_STR 72

__global__ __launch_bounds__(256)
void gemm_tf32_kernel(const float* __restrict__ W, const float* __restrict__ bias,
                      const float* __restrict__ X, float* __restrict__ out, int K)
{
  __shared__ float ws[64*WS_STR];
  __shared__ float xs[64*XS_STR];
  const int M  = gridDim.y * 64;
  const int b  = blockIdx.z;
  const int o0 = blockIdx.y * 64, n0 = blockIdx.x * 64;
  const float* Xb = X + (size_t)b * K * NTOK;
  float* Ob = out + (size_t)b * M * NTOK;
  const int tid = threadIdx.x, warp = tid >> 5, lane = tid & 31;
  const int g = lane >> 2, t = lane & 3;
  const int wm = warp & 3, wn = warp >> 2;

  float acc[4][4];
  #pragma unroll
  for (int nf = 0; nf < 4; nf++)
    #pragma unroll
    for (int j = 0; j < 4; j++) acc[nf][j] = 0.f;

  for (int k0 = 0; k0 < K; k0 += 64){
    __syncthreads();
    #pragma unroll
    for (int i = tid; i < 1024; i += 256){
      int o = i >> 4, f = i & 15;
      *(float4*)(ws + o*WS_STR + 4*f) =
          *(const float4*)(W + (size_t)(o0 + o)*K + k0 + 4*f);
    }
    #pragma unroll
    for (int i = tid; i < 1024; i += 256){
      int k = i >> 4, f = i & 15;
      *(float4*)(xs + k*XS_STR + 4*f) =
          *(const float4*)(Xb + (size_t)(k0 + k)*NTOK + n0 + 4*f);
    }
    __syncthreads();
    #pragma unroll
    for (int kk = 0; kk < 8; kk++){
      float a0f = ws[(16*wm + g    )*WS_STR + 8*kk + t];
      float a1f = ws[(16*wm + g + 8)*WS_STR + 8*kk + t];
      float a2f = ws[(16*wm + g    )*WS_STR + 8*kk + t + 4];
      float a3f = ws[(16*wm + g + 8)*WS_STR + 8*kk + t + 4];
      unsigned a0h,a0l,a1h,a1l,a2h,a2l,a3h,a3l;
      split_tf32(a0f, a0h, a0l); split_tf32(a1f, a1h, a1l);
      split_tf32(a2f, a2h, a2l); split_tf32(a3f, a3h, a3l);
      #pragma unroll
      for (int nf = 0; nf < 4; nf++){
        float b0f = xs[(8*kk + t    )*XS_STR + 32*wn + 8*nf + g];
        float b1f = xs[(8*kk + t + 4)*XS_STR + 32*wn + 8*nf + g];
        unsigned b0h,b0l,b1h,b1l;
        split_tf32(b0f, b0h, b0l); split_tf32(b1f, b1h, b1l);
        mma_tf32(acc[nf], a0h,a1h,a2h,a3h, b0h,b1h);
        mma_tf32(acc[nf], a0h,a1h,a2h,a3h, b0l,b1l);
        mma_tf32(acc[nf], a0l,a1l,a2l,a3l, b0h,b1h);
      }
    }
  }
  const int r0 = o0 + 16*wm + g, r1 = r0 + 8;
  const float bb0 = bias[r0], bb1 = bias[r1];
  #pragma unroll
  for (int nf = 0; nf < 4; nf++){
    int col = n0 + 32*wn + 8*nf + 2*t;
    float2 v0 = make_float2(acc[nf][0] + bb0, acc[nf][1] + bb0);
    float2 v1 = make_float2(acc[nf][2] + bb1, acc[nf][3] + bb1);
    *(float2*)(Ob + (size_t)r0*NTOK + col) = v0;
    *(float2*)(Ob + (size_t)r1*NTOK + col) = v1;
  }
}

// ---------------------------------------------------------------------------
// tf32 flash attention, split-KV.
// grid (NTOK/64, B, 2), 128 threads (4 warps, 16 query rows each).
// blockIdx.z = h selects KV half [h*2048, h*2048+2048).
// Writes unnormalized O to g_part and (m,l) to g_ml.
// ---------------------------------------------------------------------------
#define QS_STR 68
#define KS_STR 72
#define VS_STR 76

__global__ __launch_bounds__(128)
void flash_tf32_kernel()
{
  extern __shared__ float smf[];
  float* qs = smf;                      // 64*68
  float* ks = smf + 64*QS_STR;          // 64*72
  float* vs = ks + 64*KS_STR;           // 64*76

  const int b  = blockIdx.y;
  const int n0 = blockIdx.x * 64;
  const int h  = blockIdx.z;
  const float* gq = &g_qkv[b][0][0];
  const float* gk = &g_qkv[b][64][0];
  const float* gv = &g_qkv[b][128][0];

  const int tid  = threadIdx.x;
  const int warp = tid >> 5, lane = tid & 31;
  const int g = lane >> 2, t = lane & 3;

  // Q fill: transpose [c][n] -> qs[n][c], fold 0.125 scale, round to tf32
  #pragma unroll
  for (int i = tid; i < 1024; i += 128){
    int c = i >> 4, f = i & 15;
    float4 v = *(const float4*)(gq + c*NTOK + n0 + 4*f);
    qs[(4*f+0)*QS_STR + c] = cvt_tf32f(v.x * 0.125f);
    qs[(4*f+1)*QS_STR + c] = cvt_tf32f(v.y * 0.125f);
    qs[(4*f+2)*QS_STR + c] = cvt_tf32f(v.z * 0.125f);
    qs[(4*f+3)*QS_STR + c] = cvt_tf32f(v.w * 0.125f);
  }

  float row_m0 = -1e30f, row_m1 = -1e30f;
  float row_l0 = 0.f,    row_l1 = 0.f;
  float oacc[8][4];
  #pragma unroll
  for (int cf = 0; cf < 8; cf++)
    #pragma unroll
    for (int j = 0; j < 4; j++) oacc[cf][j] = 0.f;

  const int arow0 = (16*warp + g) * QS_STR;
  const int arow1 = (16*warp + g + 8) * QS_STR;
  const int mbeg = h * 2048, mend = mbeg + 2048;

  for (int m0 = mbeg; m0 < mend; m0 += 64){
    __syncthreads();
    #pragma unroll
    for (int i = tid; i < 1024; i += 128){
      int c = i >> 4, f = i & 15;
      float4 kv = *(const float4*)(gk + c*NTOK + m0 + 4*f);
      float* kp = ks + c*KS_STR + 4*f;
      kp[0] = cvt_tf32f(kv.x); kp[1] = cvt_tf32f(kv.y);
      kp[2] = cvt_tf32f(kv.z); kp[3] = cvt_tf32f(kv.w);
      float4 vv = *(const float4*)(gv + c*NTOK + m0 + 4*f);
      float* vp = vs + c*VS_STR + 4*f;
      vp[0] = cvt_tf32f(vv.x); vp[1] = cvt_tf32f(vv.y);
      vp[2] = cvt_tf32f(vv.z); vp[3] = cvt_tf32f(vv.w);
    }
    __syncthreads();

    // ---- S = Q^T K ----
    float sacc[8][4];
    #pragma unroll
    for (int mf = 0; mf < 8; mf++)
      #pragma unroll
      for (int j = 0; j < 4; j++) sacc[mf][j] = 0.f;

    #pragma unroll
    for (int kk = 0; kk < 8; kk++){
      unsigned a0 = __float_as_uint(qs[arow0 + 8*kk + t]);
      unsigned a1 = __float_as_uint(qs[arow1 + 8*kk + t]);
      unsigned a2 = __float_as_uint(qs[arow0 + 8*kk + t + 4]);
      unsigned a3 = __float_as_uint(qs[arow1 + 8*kk + t + 4]);
      #pragma unroll
      for (int mf = 0; mf < 8; mf++){
        unsigned b0 = __float_as_uint(ks[(8*kk + t    )*KS_STR + 8*mf + g]);
        unsigned b1 = __float_as_uint(ks[(8*kk + t + 4)*KS_STR + 8*mf + g]);
        mma_tf32(sacc[mf], a0, a1, a2, a3, b0, b1);
      }
    }

    // ---- online softmax ----
    float tm0 = -1e30f, tm1 = -1e30f;
    #pragma unroll
    for (int mf = 0; mf < 8; mf++){
      tm0 = fmaxf(tm0, fmaxf(sacc[mf][0], sacc[mf][1]));
      tm1 = fmaxf(tm1, fmaxf(sacc[mf][2], sacc[mf][3]));
    }
    tm0 = fmaxf(tm0, __shfl_xor_sync(0xffffffffu, tm0, 1));
    tm0 = fmaxf(tm0, __shfl_xor_sync(0xffffffffu, tm0, 2));
    tm1 = fmaxf(tm1, __shfl_xor_sync(0xffffffffu, tm1, 1));
    tm1 = fmaxf(tm1, __shfl_xor_sync(0xffffffffu, tm1, 2));

    float nm0 = fmaxf(row_m0, tm0), nm1 = fmaxf(row_m1, tm1);
    float al0 = __expf(row_m0 - nm0), al1 = __expf(row_m1 - nm1);
    row_m0 = nm0; row_m1 = nm1;

    float rs0 = 0.f, rs1 = 0.f;
    #pragma unroll
    for (int mf = 0; mf < 8; mf++){
      float p0 = __expf(sacc[mf][0] - nm0); rs0 += p0; sacc[mf][0] = p0;
      float p1 = __expf(sacc[mf][1] - nm0); rs0 += p1; sacc[mf][1] = p1;
      float p2 = __expf(sacc[mf][2] - nm1); rs1 += p2; sacc[mf][2] = p2;
      float p3 = __expf(sacc[mf][3] - nm1); rs1 += p3; sacc[mf][3] = p3;
    }
    rs0 += __shfl_xor_sync(0xffffffffu, rs0, 1);
    rs0 += __shfl_xor_sync(0xffffffffu, rs0, 2);
    rs1 += __shfl_xor_sync(0xffffffffu, rs1, 1);
    rs1 += __shfl_xor_sync(0xffffffffu, rs1, 2);
    row_l0 = row_l0 * al0 + rs0;
    row_l1 = row_l1 * al1 + rs1;

    #pragma unroll
    for (int cf = 0; cf < 8; cf++){
      oacc[cf][0] *= al0; oacc[cf][1] *= al0;
      oacc[cf][2] *= al1; oacc[cf][3] *= al1;
    }

    // ---- O += P V : P A-frags via shuffle of sacc, tf32-convert in place ----
    const int lA = (g << 2) + (t >> 1);
    const int lB = lA + 2;
    const bool odd = (t & 1);
    #pragma unroll
    for (int kk = 0; kk < 8; kk++){
      float x0 = __shfl_sync(0xffffffffu, sacc[kk][0], lA);
      float x1 = __shfl_sync(0xffffffffu, sacc[kk][1], lA);
      float x2 = __shfl_sync(0xffffffffu, sacc[kk][2], lA);
      float x3 = __shfl_sync(0xffffffffu, sacc[kk][3], lA);
      float y0 = __shfl_sync(0xffffffffu, sacc[kk][0], lB);
      float y1 = __shfl_sync(0xffffffffu, sacc[kk][1], lB);
      float y2 = __shfl_sync(0xffffffffu, sacc[kk][2], lB);
      float y3 = __shfl_sync(0xffffffffu, sacc[kk][3], lB);
      unsigned a0 = cvt_tf32u(odd ? x1 : x0);
      unsigned a1 = cvt_tf32u(odd ? x3 : x2);
      unsigned a2 = cvt_tf32u(odd ? y1 : y0);
      unsigned a3 = cvt_tf32u(odd ? y3 : y2);
      #pragma unroll
      for (int cf = 0; cf < 8; cf++){
        unsigned b0 = __float_as_uint(vs[(8*cf + g)*VS_STR + 8*kk + t]);
        unsigned b1 = __float_as_uint(vs[(8*cf + g)*VS_STR + 8*kk + t + 4]);
        mma_tf32(oacc[cf], a0, a1, a2, a3, b0, b1);
      }
    }
  }

  // ---- epilogue: write unnormalized partials + (m,l) ----
  int ng = n0 + 16*warp + g;
  #pragma unroll
  for (int cf = 0; cf < 8; cf++){
    int c0 = 8*cf + 2*t;
    g_part[h][b][c0    ][ng    ] = oacc[cf][0];
    g_part[h][b][c0 + 1][ng    ] = oacc[cf][1];
    g_part[h][b][c0    ][ng + 8] = oacc[cf][2];
    g_part[h][b][c0 + 1][ng + 8] = oacc[cf][3];
  }
  if (t == 0){
    g_ml[h][b][0][ng]     = row_m0;
    g_ml[h][b][1][ng]     = row_l0;
    g_ml[h][b][0][ng + 8] = row_m1;
    g_ml[h][b][1][ng + 8] = row_l1;
  }
}

// ---------------------------------------------------------------------------
// Combine the two KV-half partials.  grid (4, B), 256 threads, float4 over n.
// ---------------------------------------------------------------------------
__global__ __launch_bounds__(256)
void combine_kernel()
{
  const int b = blockIdx.y;
  const int n = blockIdx.x * 1024 + 4 * threadIdx.x;
  float4 m0 = *(const float4*)&g_ml[0][b][0][n];
  float4 l0 = *(const float4*)&g_ml[0][b][1][n];
  float4 m1 = *(const float4*)&g_ml[1][b][0][n];
  float4 l1 = *(const float4*)&g_ml[1][b][1][n];
  float4 s0, s1;
  {
    float m = fmaxf(m0.x, m1.x);
    float w0 = __expf(m0.x - m), w1 = __expf(m1.x - m);
    float inv = 1.f / (l0.x*w0 + l1.x*w1);
    s0.x = w0*inv; s1.x = w1*inv;
  }{
    float m = fmaxf(m0.y, m1.y);
    float w0 = __expf(m0.y - m), w1 = __expf(m1.y - m);
    float inv = 1.f / (l0.y*w0 + l1.y*w1);
    s0.y = w0*inv; s1.y = w1*inv;
  }{
    float m = fmaxf(m0.z, m1.z);
    float w0 = __expf(m0.z - m), w1 = __expf(m1.z - m);
    float inv = 1.f / (l0.z*w0 + l1.z*w1);
    s0.z = w0*inv; s1.z = w1*inv;
  }{
    float m = fmaxf(m0.w, m1.w);
    float w0 = __expf(m0.w - m), w1 = __expf(m1.w - m);
    float inv = 1.f / (l0.w*w0 + l1.w*w1);
    s0.w = w0*inv; s1.w = w1*inv;
  }
  #pragma unroll 4
  for (int c = 0; c < 64; c++){
    float4 p0 = *(const float4*)&g_part[0][b][c][n];
    float4 p1 = *(const float4*)&g_part[1][b][c][n];
    float4 o;
    o.x = p0.x*s0.x + p1.x*s1.x;
    o.y = p0.y*s0.y + p1.y*s1.y;
    o.z = p0.z*s0.z + p1.z*s1.z;
    o.w = p0.w*s0.w + p1.w*s1.w;
    *(float4*)&g_att[b][c][n] = o;
  }
}

// ---------------------------------------------------------------------------
extern "C" void kernel_launch(void* const* d_in, const int* in_sizes, int n_in,
                              void* d_out, int out_size)
{
  const float* x      = (const float*)d_in[0];
  const float* qkv_w  = (const float*)d_in[1];
  const float* qkv_b  = (const float*)d_in[2];
  const float* proj_w = (const float*)d_in[3];
  const float* proj_b = (const float*)d_in[4];
  float* out = (float*)d_out;

  void* qkv_ptr = 0; cudaGetSymbolAddress(&qkv_ptr, g_qkv);
  void* att_ptr = 0; cudaGetSymbolAddress(&att_ptr, g_att);

  const int flash_smem = (64*QS_STR + 64*KS_STR + 64*VS_STR) * 4;  // 55296 B
  cudaFuncSetAttribute(flash_tf32_kernel,
                       cudaFuncAttributeMaxDynamicSharedMemorySize, flash_smem);

  // QKV projection: M=192, K=256
  gemm_tf32_kernel<<<dim3(64, 3, 4), 256>>>(qkv_w, qkv_b, x, (float*)qkv_ptr, 256);
  // fused tf32 attention, split-KV = 2
  flash_tf32_kernel<<<dim3(NTOK/64, 4, 2), 128, flash_smem>>>();
  // merge halves
  combine_kernel<<<dim3(4, 4), 256>>>();
  // output projection: M=256, K=64
  gemm_tf32_kernel<<<dim3(64, 4, 4), 256>>>(proj_w, proj_b, (const float*)att_ptr, out, 64);
}